// round 13
// baseline (speedup 1.0000x reference)
#include <cuda_runtime.h>
#include <math.h>

#define NMAT   64          // B*H = 4*16 independent matrices
#define SLEN   2048        // rows per matrix
#define DDIM   128         // cols per matrix
#define RANK   64
#define KCH    4           // split-K chunks for Gram
#define SROWS  (SLEN/KCH)  // 512 rows per chunk
#define MAXSWEEPS 7        // R4-proven — do not touch
#define JTH    4e-13f      // R4-proven rotation threshold — do not touch

typedef unsigned long long u64;

// scratch (static device globals — no allocations)
__device__ float g_gpart[(size_t)NMAT * KCH * DDIM * DDIM]; // 16 MB Gram partials
__device__ float g_P[(size_t)NMAT * DDIM * DDIM];           // 4 MB projectors

// ---- packed f32x2 helpers (PTX-only; ptxas won't auto-fuse) -----------------
__device__ __forceinline__ u64 pk2(float a, float b) {
    u64 r; asm("mov.b64 %0, {%1, %2};" : "=l"(r) : "f"(a), "f"(b)); return r;
}
__device__ __forceinline__ void upk2(u64 v, float& a, float& b) {
    asm("mov.b64 {%0, %1}, %2;" : "=f"(a), "=f"(b) : "l"(v));
}
__device__ __forceinline__ u64 fma2(u64 a, u64 b, u64 c) {
    u64 d; asm("fma.rn.f32x2 %0, %1, %2, %3;" : "=l"(d) : "l"(a), "l"(b), "l"(c)); return d;
}

// ---------------------------------------------------------------------------
// Kernel 1: partial Gram  G_m += X_chunk^T X_chunk   (fp32, FFMA2 inner loop)
// grid (KCH, NMAT), 256 threads, 8x8 output tile per thread.
// ---------------------------------------------------------------------------
__global__ __launch_bounds__(256) void gram_partial_kernel(const float* __restrict__ X)
{
    __shared__ float Xs[32 * 128];
    const int m  = blockIdx.y;
    const int kc = blockIdx.x;
    const float* Xm = X + (size_t)m * SLEN * DDIM;
    const int tid = threadIdx.x;
    const int tx = tid & 15, ty = tid >> 4;

    u64 acc2[8][4];
#pragma unroll
    for (int i = 0; i < 8; i++)
#pragma unroll
        for (int j = 0; j < 4; j++) acc2[i][j] = 0ULL;

    const int s0 = kc * SROWS;
    for (int it = 0; it < SROWS / 32; ++it) {
#pragma unroll
        for (int k = 0; k < 4; k++) {
            int idx = tid + k * 256;            // float4 index within 32x128 tile
            int row = idx >> 5, c4 = idx & 31;
            float4 v = *(const float4*)(Xm + (size_t)(s0 + it * 32 + row) * DDIM + c4 * 4);
            *(float4*)(Xs + row * 128 + c4 * 4) = v;
        }
        __syncthreads();
#pragma unroll
        for (int s = 0; s < 32; s++) {
            float a[8];
            *(float4*)(a)     = *(const float4*)(Xs + s * 128 + ty * 8);
            *(float4*)(a + 4) = *(const float4*)(Xs + s * 128 + ty * 8 + 4);
            const u64* bp = (const u64*)(Xs + s * 128 + tx * 8);
            u64 b2[4];
            b2[0] = bp[0]; b2[1] = bp[1]; b2[2] = bp[2]; b2[3] = bp[3];
#pragma unroll
            for (int i = 0; i < 8; i++) {
                u64 a2 = pk2(a[i], a[i]);
#pragma unroll
                for (int j = 0; j < 4; j++)
                    acc2[i][j] = fma2(a2, b2[j], acc2[i][j]);
            }
        }
        __syncthreads();
    }

    float* out = g_gpart + ((size_t)m * KCH + kc) * DDIM * DDIM;
#pragma unroll
    for (int i = 0; i < 8; i++) {
        float x0, x1, x2, x3;
        upk2(acc2[i][0], x0, x1); upk2(acc2[i][1], x2, x3);
        *(float4*)(out + (ty * 8 + i) * 128 + tx * 8) = make_float4(x0, x1, x2, x3);
        upk2(acc2[i][2], x0, x1); upk2(acc2[i][3], x2, x3);
        *(float4*)(out + (ty * 8 + i) * 128 + tx * 8 + 4) = make_float4(x0, x1, x2, x3);
    }
}

// ---------------------------------------------------------------------------
// Kernel 2: one-sided Jacobi on G (128x128) per matrix; emits projector P.
// 64 blocks x 512 threads — exact R4 round structure (proven fastest).
// New: STABILITY-SKIP. Every pair is examined every sweep; a pair whose
// last examination produced no rotation, and whose columns have not been
// rotated since (rot_prev / rot_cur flags), has an unchanged dot that is
// still below threshold -> skip its loads and dot entirely. The applied
// rotation sequence is identical to R4; only provable no-ops are elided.
// ---------------------------------------------------------------------------
__global__ __launch_bounds__(512) void jacobi_kernel()
{
    extern __shared__ float B[];     // [128 cols][128 rows], col-major
    __shared__ float nrm2[128];
    __shared__ float wsel[128];
    __shared__ int rot_prev[128];    // column rotated during previous sweep
    __shared__ int rot_cur[128];     // column rotated so far this sweep
    __shared__ int any_rot;

    const int m   = blockIdx.x;
    const int tid = threadIdx.x;

    // load + reduce split-K partials directly into SMEM (G symmetric, so
    // row-major source == col-major dest)
    const float* gp = g_gpart + (size_t)m * KCH * DDIM * DDIM;
#pragma unroll
    for (int k = 0; k < 8; k++) {
        int i4 = tid + k * 512;
        float4 s = make_float4(0.f, 0.f, 0.f, 0.f);
#pragma unroll
        for (int p = 0; p < KCH; p++) {
            float4 v = *(const float4*)(gp + (size_t)p * DDIM * DDIM + i4 * 4);
            s.x += v.x; s.y += v.y; s.z += v.z; s.w += v.w;
        }
        *(float4*)(B + i4 * 4) = s;
    }
    if (tid < 128) { rot_prev[tid] = 1; rot_cur[tid] = 0; }   // all dirty at start
    __syncthreads();

    const int pairIdx = tid >> 3;   // 0..63
    const int sub     = tid & 7;    // 8 threads per pair

    for (int sweep = 0; sweep < MAXSWEEPS; ++sweep) {
        // exact column norms (fixes incremental drift each sweep)
        {
            int col = tid >> 2, part = tid & 3;
            const float* bc = B + col * 128;
            float ss = 0.f;
#pragma unroll
            for (int k = 0; k < 8; k++) {
                float4 v = *(const float4*)(bc + (k * 4 + part) * 4);
                ss += v.x * v.x + v.y * v.y + v.z * v.z + v.w * v.w;
            }
            ss += __shfl_xor_sync(0xffffffffu, ss, 1);
            ss += __shfl_xor_sync(0xffffffffu, ss, 2);
            if (part == 0) nrm2[col] = ss;
            if (tid == 0) any_rot = 0;
        }
        // roll stability flags: prev <- cur, cur <- 0 (skip on sweep 0: done above)
        if (sweep > 0 && tid < 128) {
            rot_prev[tid] = rot_cur[tid];
            rot_cur[tid]  = 0;
        }
        __syncthreads();

        for (int r = 0; r < 127; r++) {
            // round-robin tournament pairing (player 127 fixed)
            int p, q;
            if (pairIdx == 0) { p = 127; q = r; }
            else {
                p = r + pairIdx;        if (p >= 127) p -= 127;
                q = r + 127 - pairIdx;  if (q >= 127) q -= 127;
            }

            // stability-skip: dot unchanged since last (no-rotate) examination
            int dirty = rot_prev[p] | rot_prev[q] | rot_cur[p] | rot_cur[q];
            if (dirty) {
                float* bp = B + p * 128 + sub * 4;
                float* bq = B + q * 128 + sub * 4;
                float4 p4[4], q4[4];
#pragma unroll
                for (int k = 0; k < 4; k++) {
                    p4[k] = *(const float4*)(bp + k * 32);
                    q4[k] = *(const float4*)(bq + k * 32);
                }
                float g = 0.f;
#pragma unroll
                for (int k = 0; k < 4; k++)
                    g += p4[k].x * q4[k].x + p4[k].y * q4[k].y +
                         p4[k].z * q4[k].z + p4[k].w * q4[k].w;
                g += __shfl_xor_sync(0xffffffffu, g, 1);
                g += __shfl_xor_sync(0xffffffffu, g, 2);
                g += __shfl_xor_sync(0xffffffffu, g, 4);

                float al = nrm2[p], be = nrm2[q];
                if (g * g > JTH * al * be) {   // uniform within the 8-lane group
                    float zeta = (be - al) / (2.f * g);
                    float t = 1.f / (fabsf(zeta) + sqrtf(1.f + zeta * zeta));
                    t = (zeta < 0.f) ? -t : t;
                    float c  = rsqrtf(1.f + t * t);
                    float sn = c * t;
#pragma unroll
                    for (int k = 0; k < 4; k++) {
                        float4 np, nq;
                        np.x = c * p4[k].x - sn * q4[k].x;  nq.x = sn * p4[k].x + c * q4[k].x;
                        np.y = c * p4[k].y - sn * q4[k].y;  nq.y = sn * p4[k].y + c * q4[k].y;
                        np.z = c * p4[k].z - sn * q4[k].z;  nq.z = sn * p4[k].z + c * q4[k].z;
                        np.w = c * p4[k].w - sn * q4[k].w;  nq.w = sn * p4[k].w + c * q4[k].w;
                        *(float4*)(bp + k * 32) = np;
                        *(float4*)(bq + k * 32) = nq;
                    }
                    if (sub == 0) {
                        nrm2[p] = al - t * g;
                        nrm2[q] = be + t * g;
                        rot_cur[p] = 1;
                        rot_cur[q] = 1;
                        any_rot = 1;          // benign same-value race
                    }
                }
            }
            __syncthreads();
        }

        // early exit: last round's barrier makes any_rot coherent here.
        int rot = any_rot;
        __syncthreads();          // protect against next sweep's reset racing
        if (!rot) break;
    }

    // final exact norms (||b_k||^2 = lambda_k^2)
    {
        int col = tid >> 2, part = tid & 3;
        const float* bc = B + col * 128;
        float ss = 0.f;
#pragma unroll
        for (int k = 0; k < 8; k++) {
            float4 v = *(const float4*)(bc + (k * 4 + part) * 4);
            ss += v.x * v.x + v.y * v.y + v.z * v.z + v.w * v.w;
        }
        ss += __shfl_xor_sync(0xffffffffu, ss, 1);
        ss += __shfl_xor_sync(0xffffffffu, ss, 2);
        if (part == 0) nrm2[col] = ss;
    }
    __syncthreads();

    // select top-RANK columns by norm; weight = 1/||b||^2 so P = sum w b b^T
    if (tid < 128) {
        float nj = nrm2[tid];
        int rk = 0;
        for (int i = 0; i < 128; i++) {
            float ni = nrm2[i];
            rk += (ni > nj) || (ni == nj && i < tid);
        }
        wsel[tid] = (rk < RANK) ? 1.f / nj : 0.f;
    }
    __syncthreads();

    // P[r][c] = sum_j w_j * B[j][r] * B[j][c]
    {
        int tx = tid & 31, ty = tid >> 5;     // 32 x 16 thread grid
        int c0 = tx * 4, r0 = ty * 8;
        float acc[8][4];
#pragma unroll
        for (int i = 0; i < 8; i++)
#pragma unroll
            for (int l = 0; l < 4; l++) acc[i][l] = 0.f;

        for (int j = 0; j < 128; j++) {
            float wj = wsel[j];
            if (wj == 0.f) continue;          // uniform branch: halves work
            const float* bj = B + j * 128;
            float br[8];
            *(float4*)(br)     = *(const float4*)(bj + r0);
            *(float4*)(br + 4) = *(const float4*)(bj + r0 + 4);
            float4 bc4 = *(const float4*)(bj + c0);
            bc4.x *= wj; bc4.y *= wj; bc4.z *= wj; bc4.w *= wj;
#pragma unroll
            for (int i = 0; i < 8; i++) {
                acc[i][0] += br[i] * bc4.x;
                acc[i][1] += br[i] * bc4.y;
                acc[i][2] += br[i] * bc4.z;
                acc[i][3] += br[i] * bc4.w;
            }
        }
        float* Pm = g_P + (size_t)m * DDIM * DDIM;
#pragma unroll
        for (int i = 0; i < 8; i++)
            *(float4*)(Pm + (r0 + i) * 128 + c0) =
                make_float4(acc[i][0], acc[i][1], acc[i][2], acc[i][3]);
    }
}

// ---------------------------------------------------------------------------
// Kernel 3: out = X @ P  (fp32, FFMA2 inner loop). grid (32, NMAT),
// 256 threads, 64-row tiles; k unrolled by 4 with float4 A loads.
// ---------------------------------------------------------------------------
__global__ __launch_bounds__(256) void recon_kernel(const float* __restrict__ X,
                                                    float* __restrict__ out)
{
    extern __shared__ float sm[];
    float* Ps = sm;          // 128*128
    float* Xs = sm + 16384;  // 64*128
    const int m  = blockIdx.y;
    const int s0 = blockIdx.x * 64;
    const int tid = threadIdx.x;

    const float* Pm = g_P + (size_t)m * DDIM * DDIM;
#pragma unroll
    for (int k = 0; k < 16; k++) {
        int i4 = tid + k * 256;
        *(float4*)(Ps + i4 * 4) = *(const float4*)(Pm + i4 * 4);
    }
    const float* Xm = X + (size_t)m * SLEN * DDIM + (size_t)s0 * DDIM;
#pragma unroll
    for (int k = 0; k < 8; k++) {
        int i4 = tid + k * 256;
        *(float4*)(Xs + i4 * 4) = *(const float4*)(Xm + i4 * 4);
    }
    __syncthreads();

    const int tx = tid & 31, ty = tid >> 5;   // 32 x 8
    const int c0 = tx * 4, r0 = ty * 8;
    u64 acc2[8][2];
#pragma unroll
    for (int i = 0; i < 8; i++) { acc2[i][0] = 0ULL; acc2[i][1] = 0ULL; }

#pragma unroll 1
    for (int k0 = 0; k0 < 128; k0 += 4) {
        float4 a4[8];
#pragma unroll
        for (int i = 0; i < 8; i++)
            a4[i] = *(const float4*)(Xs + (r0 + i) * 128 + k0);
#pragma unroll
        for (int kk = 0; kk < 4; kk++) {
            const u64* bp = (const u64*)(Ps + (k0 + kk) * 128 + c0);
            u64 b0 = bp[0], b1 = bp[1];
#pragma unroll
            for (int i = 0; i < 8; i++) {
                float av = (kk == 0) ? a4[i].x : (kk == 1) ? a4[i].y
                         : (kk == 2) ? a4[i].z : a4[i].w;
                u64 a2 = pk2(av, av);
                acc2[i][0] = fma2(a2, b0, acc2[i][0]);
                acc2[i][1] = fma2(a2, b1, acc2[i][1]);
            }
        }
    }

    float* outm = out + (size_t)m * SLEN * DDIM + (size_t)s0 * DDIM;
#pragma unroll
    for (int i = 0; i < 8; i++) {
        float x0, x1, x2, x3;
        upk2(acc2[i][0], x0, x1); upk2(acc2[i][1], x2, x3);
        *(float4*)(outm + (r0 + i) * 128 + c0) = make_float4(x0, x1, x2, x3);
    }
}

// ---------------------------------------------------------------------------
extern "C" void kernel_launch(void* const* d_in, const int* in_sizes, int n_in,
                              void* d_out, int out_size)
{
    const float* X = (const float*)d_in[0];
    float* out = (float*)d_out;

    cudaFuncSetAttribute(jacobi_kernel, cudaFuncAttributeMaxDynamicSharedMemorySize,
                         128 * 128 * 4);
    cudaFuncSetAttribute(recon_kernel, cudaFuncAttributeMaxDynamicSharedMemorySize,
                         (16384 + 8192) * 4);

    gram_partial_kernel<<<dim3(KCH, NMAT), 256>>>(X);
    jacobi_kernel<<<NMAT, 512, 128 * 128 * 4>>>();
    recon_kernel<<<dim3(SLEN / 64, NMAT), 256, (16384 + 8192) * 4>>>(X, out);
}

// round 14
// speedup vs baseline: 1.0005x; 1.0005x over previous
#include <cuda_runtime.h>
#include <math.h>

#define NMAT   64          // B*H = 4*16 independent matrices
#define SLEN   2048        // rows per matrix
#define DDIM   128         // cols per matrix
#define RANK   64
#define KCH    4           // split-K chunks for Gram
#define SROWS  (SLEN/KCH)  // 512 rows per chunk
#define MAXSWEEPS 7        // R4-proven — do not touch
#define JTH    4e-13f      // R4-proven rotation threshold — do not touch

typedef unsigned long long u64;

// scratch (static device globals — no allocations)
__device__ float g_gpart[(size_t)NMAT * KCH * DDIM * DDIM]; // 16 MB Gram partials
__device__ float g_P[(size_t)NMAT * DDIM * DDIM];           // 4 MB projectors

// ---- packed f32x2 helpers (PTX-only; ptxas won't auto-fuse) -----------------
__device__ __forceinline__ u64 pk2(float a, float b) {
    u64 r; asm("mov.b64 %0, {%1, %2};" : "=l"(r) : "f"(a), "f"(b)); return r;
}
__device__ __forceinline__ void upk2(u64 v, float& a, float& b) {
    asm("mov.b64 {%0, %1}, %2;" : "=f"(a), "=f"(b) : "l"(v));
}
__device__ __forceinline__ u64 fma2(u64 a, u64 b, u64 c) {
    u64 d; asm("fma.rn.f32x2 %0, %1, %2, %3;" : "=l"(d) : "l"(a), "l"(b), "l"(c)); return d;
}

// ---------------------------------------------------------------------------
// Kernel 1: partial Gram  G_m += X_chunk^T X_chunk   (fp32, FFMA2 inner loop)
// grid (KCH, NMAT), 256 threads, 8x8 output tile per thread.
// ---------------------------------------------------------------------------
__global__ __launch_bounds__(256) void gram_partial_kernel(const float* __restrict__ X)
{
    __shared__ float Xs[32 * 128];
    const int m  = blockIdx.y;
    const int kc = blockIdx.x;
    const float* Xm = X + (size_t)m * SLEN * DDIM;
    const int tid = threadIdx.x;
    const int tx = tid & 15, ty = tid >> 4;

    u64 acc2[8][4];
#pragma unroll
    for (int i = 0; i < 8; i++)
#pragma unroll
        for (int j = 0; j < 4; j++) acc2[i][j] = 0ULL;

    const int s0 = kc * SROWS;
    for (int it = 0; it < SROWS / 32; ++it) {
#pragma unroll
        for (int k = 0; k < 4; k++) {
            int idx = tid + k * 256;            // float4 index within 32x128 tile
            int row = idx >> 5, c4 = idx & 31;
            float4 v = *(const float4*)(Xm + (size_t)(s0 + it * 32 + row) * DDIM + c4 * 4);
            *(float4*)(Xs + row * 128 + c4 * 4) = v;
        }
        __syncthreads();
#pragma unroll
        for (int s = 0; s < 32; s++) {
            float a[8];
            *(float4*)(a)     = *(const float4*)(Xs + s * 128 + ty * 8);
            *(float4*)(a + 4) = *(const float4*)(Xs + s * 128 + ty * 8 + 4);
            const u64* bp = (const u64*)(Xs + s * 128 + tx * 8);
            u64 b2[4];
            b2[0] = bp[0]; b2[1] = bp[1]; b2[2] = bp[2]; b2[3] = bp[3];
#pragma unroll
            for (int i = 0; i < 8; i++) {
                u64 a2 = pk2(a[i], a[i]);
#pragma unroll
                for (int j = 0; j < 4; j++)
                    acc2[i][j] = fma2(a2, b2[j], acc2[i][j]);
            }
        }
        __syncthreads();
    }

    float* out = g_gpart + ((size_t)m * KCH + kc) * DDIM * DDIM;
#pragma unroll
    for (int i = 0; i < 8; i++) {
        float x0, x1, x2, x3;
        upk2(acc2[i][0], x0, x1); upk2(acc2[i][1], x2, x3);
        *(float4*)(out + (ty * 8 + i) * 128 + tx * 8) = make_float4(x0, x1, x2, x3);
        upk2(acc2[i][2], x0, x1); upk2(acc2[i][3], x2, x3);
        *(float4*)(out + (ty * 8 + i) * 128 + tx * 8 + 4) = make_float4(x0, x1, x2, x3);
    }
}

// ---------------------------------------------------------------------------
// Kernel 2: one-sided Jacobi on G (128x128) per matrix; emits projector P.
// 64 blocks x 512 threads — exact R4 round structure (proven fastest).
// New: STABILITY-SKIP. Every pair is examined every sweep; a pair whose
// last examination produced no rotation, and whose columns have not been
// rotated since (rot_prev / rot_cur flags), has an unchanged dot that is
// still below threshold -> skip its loads and dot entirely. The applied
// rotation sequence is identical to R4; only provable no-ops are elided.
// ---------------------------------------------------------------------------
__global__ __launch_bounds__(512) void jacobi_kernel()
{
    extern __shared__ float B[];     // [128 cols][128 rows], col-major
    __shared__ float nrm2[128];
    __shared__ float wsel[128];
    __shared__ int rot_prev[128];    // column rotated during previous sweep
    __shared__ int rot_cur[128];     // column rotated so far this sweep
    __shared__ int any_rot;

    const int m   = blockIdx.x;
    const int tid = threadIdx.x;

    // load + reduce split-K partials directly into SMEM (G symmetric, so
    // row-major source == col-major dest)
    const float* gp = g_gpart + (size_t)m * KCH * DDIM * DDIM;
#pragma unroll
    for (int k = 0; k < 8; k++) {
        int i4 = tid + k * 512;
        float4 s = make_float4(0.f, 0.f, 0.f, 0.f);
#pragma unroll
        for (int p = 0; p < KCH; p++) {
            float4 v = *(const float4*)(gp + (size_t)p * DDIM * DDIM + i4 * 4);
            s.x += v.x; s.y += v.y; s.z += v.z; s.w += v.w;
        }
        *(float4*)(B + i4 * 4) = s;
    }
    if (tid < 128) { rot_prev[tid] = 1; rot_cur[tid] = 0; }   // all dirty at start
    __syncthreads();

    const int pairIdx = tid >> 3;   // 0..63
    const int sub     = tid & 7;    // 8 threads per pair

    for (int sweep = 0; sweep < MAXSWEEPS; ++sweep) {
        // exact column norms (fixes incremental drift each sweep)
        {
            int col = tid >> 2, part = tid & 3;
            const float* bc = B + col * 128;
            float ss = 0.f;
#pragma unroll
            for (int k = 0; k < 8; k++) {
                float4 v = *(const float4*)(bc + (k * 4 + part) * 4);
                ss += v.x * v.x + v.y * v.y + v.z * v.z + v.w * v.w;
            }
            ss += __shfl_xor_sync(0xffffffffu, ss, 1);
            ss += __shfl_xor_sync(0xffffffffu, ss, 2);
            if (part == 0) nrm2[col] = ss;
            if (tid == 0) any_rot = 0;
        }
        // roll stability flags: prev <- cur, cur <- 0 (skip on sweep 0: done above)
        if (sweep > 0 && tid < 128) {
            rot_prev[tid] = rot_cur[tid];
            rot_cur[tid]  = 0;
        }
        __syncthreads();

        for (int r = 0; r < 127; r++) {
            // round-robin tournament pairing (player 127 fixed)
            int p, q;
            if (pairIdx == 0) { p = 127; q = r; }
            else {
                p = r + pairIdx;        if (p >= 127) p -= 127;
                q = r + 127 - pairIdx;  if (q >= 127) q -= 127;
            }

            // stability-skip: dot unchanged since last (no-rotate) examination
            int dirty = rot_prev[p] | rot_prev[q] | rot_cur[p] | rot_cur[q];
            if (dirty) {
                float* bp = B + p * 128 + sub * 4;
                float* bq = B + q * 128 + sub * 4;
                float4 p4[4], q4[4];
#pragma unroll
                for (int k = 0; k < 4; k++) {
                    p4[k] = *(const float4*)(bp + k * 32);
                    q4[k] = *(const float4*)(bq + k * 32);
                }
                float g = 0.f;
#pragma unroll
                for (int k = 0; k < 4; k++)
                    g += p4[k].x * q4[k].x + p4[k].y * q4[k].y +
                         p4[k].z * q4[k].z + p4[k].w * q4[k].w;
                g += __shfl_xor_sync(0xffffffffu, g, 1);
                g += __shfl_xor_sync(0xffffffffu, g, 2);
                g += __shfl_xor_sync(0xffffffffu, g, 4);

                float al = nrm2[p], be = nrm2[q];
                if (g * g > JTH * al * be) {   // uniform within the 8-lane group
                    float zeta = (be - al) / (2.f * g);
                    float t = 1.f / (fabsf(zeta) + sqrtf(1.f + zeta * zeta));
                    t = (zeta < 0.f) ? -t : t;
                    float c  = rsqrtf(1.f + t * t);
                    float sn = c * t;
#pragma unroll
                    for (int k = 0; k < 4; k++) {
                        float4 np, nq;
                        np.x = c * p4[k].x - sn * q4[k].x;  nq.x = sn * p4[k].x + c * q4[k].x;
                        np.y = c * p4[k].y - sn * q4[k].y;  nq.y = sn * p4[k].y + c * q4[k].y;
                        np.z = c * p4[k].z - sn * q4[k].z;  nq.z = sn * p4[k].z + c * q4[k].z;
                        np.w = c * p4[k].w - sn * q4[k].w;  nq.w = sn * p4[k].w + c * q4[k].w;
                        *(float4*)(bp + k * 32) = np;
                        *(float4*)(bq + k * 32) = nq;
                    }
                    if (sub == 0) {
                        nrm2[p] = al - t * g;
                        nrm2[q] = be + t * g;
                        rot_cur[p] = 1;
                        rot_cur[q] = 1;
                        any_rot = 1;          // benign same-value race
                    }
                }
            }
            __syncthreads();
        }

        // early exit: last round's barrier makes any_rot coherent here.
        int rot = any_rot;
        __syncthreads();          // protect against next sweep's reset racing
        if (!rot) break;
    }

    // final exact norms (||b_k||^2 = lambda_k^2)
    {
        int col = tid >> 2, part = tid & 3;
        const float* bc = B + col * 128;
        float ss = 0.f;
#pragma unroll
        for (int k = 0; k < 8; k++) {
            float4 v = *(const float4*)(bc + (k * 4 + part) * 4);
            ss += v.x * v.x + v.y * v.y + v.z * v.z + v.w * v.w;
        }
        ss += __shfl_xor_sync(0xffffffffu, ss, 1);
        ss += __shfl_xor_sync(0xffffffffu, ss, 2);
        if (part == 0) nrm2[col] = ss;
    }
    __syncthreads();

    // select top-RANK columns by norm; weight = 1/||b||^2 so P = sum w b b^T
    if (tid < 128) {
        float nj = nrm2[tid];
        int rk = 0;
        for (int i = 0; i < 128; i++) {
            float ni = nrm2[i];
            rk += (ni > nj) || (ni == nj && i < tid);
        }
        wsel[tid] = (rk < RANK) ? 1.f / nj : 0.f;
    }
    __syncthreads();

    // P[r][c] = sum_j w_j * B[j][r] * B[j][c]
    {
        int tx = tid & 31, ty = tid >> 5;     // 32 x 16 thread grid
        int c0 = tx * 4, r0 = ty * 8;
        float acc[8][4];
#pragma unroll
        for (int i = 0; i < 8; i++)
#pragma unroll
            for (int l = 0; l < 4; l++) acc[i][l] = 0.f;

        for (int j = 0; j < 128; j++) {
            float wj = wsel[j];
            if (wj == 0.f) continue;          // uniform branch: halves work
            const float* bj = B + j * 128;
            float br[8];
            *(float4*)(br)     = *(const float4*)(bj + r0);
            *(float4*)(br + 4) = *(const float4*)(bj + r0 + 4);
            float4 bc4 = *(const float4*)(bj + c0);
            bc4.x *= wj; bc4.y *= wj; bc4.z *= wj; bc4.w *= wj;
#pragma unroll
            for (int i = 0; i < 8; i++) {
                acc[i][0] += br[i] * bc4.x;
                acc[i][1] += br[i] * bc4.y;
                acc[i][2] += br[i] * bc4.z;
                acc[i][3] += br[i] * bc4.w;
            }
        }
        float* Pm = g_P + (size_t)m * DDIM * DDIM;
#pragma unroll
        for (int i = 0; i < 8; i++)
            *(float4*)(Pm + (r0 + i) * 128 + c0) =
                make_float4(acc[i][0], acc[i][1], acc[i][2], acc[i][3]);
    }
}

// ---------------------------------------------------------------------------
// Kernel 3: out = X @ P  (fp32, FFMA2 inner loop). grid (32, NMAT),
// 256 threads, 64-row tiles; k unrolled by 4 with float4 A loads.
// ---------------------------------------------------------------------------
__global__ __launch_bounds__(256) void recon_kernel(const float* __restrict__ X,
                                                    float* __restrict__ out)
{
    extern __shared__ float sm[];
    float* Ps = sm;          // 128*128
    float* Xs = sm + 16384;  // 64*128
    const int m  = blockIdx.y;
    const int s0 = blockIdx.x * 64;
    const int tid = threadIdx.x;

    const float* Pm = g_P + (size_t)m * DDIM * DDIM;
#pragma unroll
    for (int k = 0; k < 16; k++) {
        int i4 = tid + k * 256;
        *(float4*)(Ps + i4 * 4) = *(const float4*)(Pm + i4 * 4);
    }
    const float* Xm = X + (size_t)m * SLEN * DDIM + (size_t)s0 * DDIM;
#pragma unroll
    for (int k = 0; k < 8; k++) {
        int i4 = tid + k * 256;
        *(float4*)(Xs + i4 * 4) = *(const float4*)(Xm + i4 * 4);
    }
    __syncthreads();

    const int tx = tid & 31, ty = tid >> 5;   // 32 x 8
    const int c0 = tx * 4, r0 = ty * 8;
    u64 acc2[8][2];
#pragma unroll
    for (int i = 0; i < 8; i++) { acc2[i][0] = 0ULL; acc2[i][1] = 0ULL; }

#pragma unroll 1
    for (int k0 = 0; k0 < 128; k0 += 4) {
        float4 a4[8];
#pragma unroll
        for (int i = 0; i < 8; i++)
            a4[i] = *(const float4*)(Xs + (r0 + i) * 128 + k0);
#pragma unroll
        for (int kk = 0; kk < 4; kk++) {
            const u64* bp = (const u64*)(Ps + (k0 + kk) * 128 + c0);
            u64 b0 = bp[0], b1 = bp[1];
#pragma unroll
            for (int i = 0; i < 8; i++) {
                float av = (kk == 0) ? a4[i].x : (kk == 1) ? a4[i].y
                         : (kk == 2) ? a4[i].z : a4[i].w;
                u64 a2 = pk2(av, av);
                acc2[i][0] = fma2(a2, b0, acc2[i][0]);
                acc2[i][1] = fma2(a2, b1, acc2[i][1]);
            }
        }
    }

    float* outm = out + (size_t)m * SLEN * DDIM + (size_t)s0 * DDIM;
#pragma unroll
    for (int i = 0; i < 8; i++) {
        float x0, x1, x2, x3;
        upk2(acc2[i][0], x0, x1); upk2(acc2[i][1], x2, x3);
        *(float4*)(outm + (r0 + i) * 128 + c0) = make_float4(x0, x1, x2, x3);
    }
}

// ---------------------------------------------------------------------------
extern "C" void kernel_launch(void* const* d_in, const int* in_sizes, int n_in,
                              void* d_out, int out_size)
{
    const float* X = (const float*)d_in[0];
    float* out = (float*)d_out;

    cudaFuncSetAttribute(jacobi_kernel, cudaFuncAttributeMaxDynamicSharedMemorySize,
                         128 * 128 * 4);
    cudaFuncSetAttribute(recon_kernel, cudaFuncAttributeMaxDynamicSharedMemorySize,
                         (16384 + 8192) * 4);

    gram_partial_kernel<<<dim3(KCH, NMAT), 256>>>(X);
    jacobi_kernel<<<NMAT, 512, 128 * 128 * 4>>>();
    recon_kernel<<<dim3(SLEN / 64, NMAT), 256, (16384 + 8192) * 4>>>(X, out);
}

// round 15
// speedup vs baseline: 1.1001x; 1.0996x over previous
#include <cuda_runtime.h>
#include <math.h>

#define NMAT   64          // B*H = 4*16 independent matrices
#define SLEN   2048        // rows per matrix
#define DDIM   128         // cols per matrix
#define RANK   64
#define KCH    4           // split-K chunks for Gram (R12-proven)
#define SROWS  (SLEN/KCH)  // 512 rows per chunk
#define MAXSWEEPS 7        // R4-proven — do not touch
#define JTH    4e-13f      // R4-proven rotation threshold — do not touch

typedef unsigned long long u64;

// scratch (static device globals — no allocations)
__device__ float g_gpart[(size_t)NMAT * KCH * DDIM * DDIM]; // 16 MB Gram partials
__device__ float g_P[(size_t)NMAT * DDIM * DDIM];           // 4 MB projectors

// ---- packed f32x2 helpers (PTX-only; ptxas won't auto-fuse) -----------------
__device__ __forceinline__ u64 pk2(float a, float b) {
    u64 r; asm("mov.b64 %0, {%1, %2};" : "=l"(r) : "f"(a), "f"(b)); return r;
}
__device__ __forceinline__ void upk2(u64 v, float& a, float& b) {
    asm("mov.b64 {%0, %1}, %2;" : "=f"(a), "=f"(b) : "l"(v));
}
__device__ __forceinline__ u64 fma2(u64 a, u64 b, u64 c) {
    u64 d; asm("fma.rn.f32x2 %0, %1, %2, %3;" : "=l"(d) : "l"(a), "l"(b), "l"(c)); return d;
}

// ---------------------------------------------------------------------------
// Kernel 1: partial Gram  G_m += X_chunk^T X_chunk   (fp32, FFMA2 inner loop)
// grid (KCH, NMAT), 256 threads, 8x8 output tile per thread.
// ---------------------------------------------------------------------------
__global__ __launch_bounds__(256) void gram_partial_kernel(const float* __restrict__ X)
{
    __shared__ float Xs[32 * 128];
    const int m  = blockIdx.y;
    const int kc = blockIdx.x;
    const float* Xm = X + (size_t)m * SLEN * DDIM;
    const int tid = threadIdx.x;
    const int tx = tid & 15, ty = tid >> 4;

    u64 acc2[8][4];
#pragma unroll
    for (int i = 0; i < 8; i++)
#pragma unroll
        for (int j = 0; j < 4; j++) acc2[i][j] = 0ULL;

    const int s0 = kc * SROWS;
    for (int it = 0; it < SROWS / 32; ++it) {
#pragma unroll
        for (int k = 0; k < 4; k++) {
            int idx = tid + k * 256;            // float4 index within 32x128 tile
            int row = idx >> 5, c4 = idx & 31;
            float4 v = *(const float4*)(Xm + (size_t)(s0 + it * 32 + row) * DDIM + c4 * 4);
            *(float4*)(Xs + row * 128 + c4 * 4) = v;
        }
        __syncthreads();
#pragma unroll
        for (int s = 0; s < 32; s++) {
            float a[8];
            *(float4*)(a)     = *(const float4*)(Xs + s * 128 + ty * 8);
            *(float4*)(a + 4) = *(const float4*)(Xs + s * 128 + ty * 8 + 4);
            const u64* bp = (const u64*)(Xs + s * 128 + tx * 8);
            u64 b2[4];
            b2[0] = bp[0]; b2[1] = bp[1]; b2[2] = bp[2]; b2[3] = bp[3];
#pragma unroll
            for (int i = 0; i < 8; i++) {
                u64 a2 = pk2(a[i], a[i]);
#pragma unroll
                for (int j = 0; j < 4; j++)
                    acc2[i][j] = fma2(a2, b2[j], acc2[i][j]);
            }
        }
        __syncthreads();
    }

    float* out = g_gpart + ((size_t)m * KCH + kc) * DDIM * DDIM;
#pragma unroll
    for (int i = 0; i < 8; i++) {
        float x0, x1, x2, x3;
        upk2(acc2[i][0], x0, x1); upk2(acc2[i][1], x2, x3);
        *(float4*)(out + (ty * 8 + i) * 128 + tx * 8) = make_float4(x0, x1, x2, x3);
        upk2(acc2[i][2], x0, x1); upk2(acc2[i][3], x2, x3);
        *(float4*)(out + (ty * 8 + i) * 128 + tx * 8 + 4) = make_float4(x0, x1, x2, x3);
    }
}

// ---------------------------------------------------------------------------
// Kernel 2: one-sided Jacobi on G (128x128) per matrix; emits projector P.
// 64 blocks x 512 threads — EXACT R7 hot loop (977us champion). 7 sweeps,
// skip threshold 4e-13 with write-back skip, early sweep exit. No flags,
// no tau, no skip arrays — 5/5 such additions regressed.
// ---------------------------------------------------------------------------
__global__ __launch_bounds__(512) void jacobi_kernel()
{
    extern __shared__ float B[];     // [128 cols][128 rows], col-major
    __shared__ float nrm2[128];
    __shared__ float wsel[128];
    __shared__ int any_rot;

    const int m   = blockIdx.x;
    const int tid = threadIdx.x;

    // load + reduce split-K partials directly into SMEM (G symmetric, so
    // row-major source == col-major dest)
    const float* gp = g_gpart + (size_t)m * KCH * DDIM * DDIM;
#pragma unroll
    for (int k = 0; k < 8; k++) {
        int i4 = tid + k * 512;
        float4 s = make_float4(0.f, 0.f, 0.f, 0.f);
#pragma unroll
        for (int p = 0; p < KCH; p++) {
            float4 v = *(const float4*)(gp + (size_t)p * DDIM * DDIM + i4 * 4);
            s.x += v.x; s.y += v.y; s.z += v.z; s.w += v.w;
        }
        *(float4*)(B + i4 * 4) = s;
    }
    __syncthreads();

    const int pairIdx = tid >> 3;   // 0..63
    const int sub     = tid & 7;    // 8 threads per pair

    for (int sweep = 0; sweep < MAXSWEEPS; ++sweep) {
        // exact column norms (fixes incremental drift each sweep)
        {
            int col = tid >> 2, part = tid & 3;
            const float* bc = B + col * 128;
            float ss = 0.f;
#pragma unroll
            for (int k = 0; k < 8; k++) {
                float4 v = *(const float4*)(bc + (k * 4 + part) * 4);
                ss += v.x * v.x + v.y * v.y + v.z * v.z + v.w * v.w;
            }
            ss += __shfl_xor_sync(0xffffffffu, ss, 1);
            ss += __shfl_xor_sync(0xffffffffu, ss, 2);
            if (part == 0) nrm2[col] = ss;
            if (tid == 0) any_rot = 0;
        }
        __syncthreads();

        for (int r = 0; r < 127; r++) {
            // round-robin tournament pairing (player 127 fixed)
            int p, q;
            if (pairIdx == 0) { p = 127; q = r; }
            else {
                p = r + pairIdx;        if (p >= 127) p -= 127;
                q = r + 127 - pairIdx;  if (q >= 127) q -= 127;
            }
            float* bp = B + p * 128 + sub * 4;
            float* bq = B + q * 128 + sub * 4;
            float4 p4[4], q4[4];
#pragma unroll
            for (int k = 0; k < 4; k++) {
                p4[k] = *(const float4*)(bp + k * 32);
                q4[k] = *(const float4*)(bq + k * 32);
            }
            float g = 0.f;
#pragma unroll
            for (int k = 0; k < 4; k++)
                g += p4[k].x * q4[k].x + p4[k].y * q4[k].y +
                     p4[k].z * q4[k].z + p4[k].w * q4[k].w;
            g += __shfl_xor_sync(0xffffffffu, g, 1);
            g += __shfl_xor_sync(0xffffffffu, g, 2);
            g += __shfl_xor_sync(0xffffffffu, g, 4);

            float al = nrm2[p], be = nrm2[q];
            if (g * g > JTH * al * be) {   // uniform within the 8-lane group
                float zeta = (be - al) / (2.f * g);
                float t = 1.f / (fabsf(zeta) + sqrtf(1.f + zeta * zeta));
                t = (zeta < 0.f) ? -t : t;
                float c  = rsqrtf(1.f + t * t);
                float sn = c * t;
#pragma unroll
                for (int k = 0; k < 4; k++) {
                    float4 np, nq;
                    np.x = c * p4[k].x - sn * q4[k].x;  nq.x = sn * p4[k].x + c * q4[k].x;
                    np.y = c * p4[k].y - sn * q4[k].y;  nq.y = sn * p4[k].y + c * q4[k].y;
                    np.z = c * p4[k].z - sn * q4[k].z;  nq.z = sn * p4[k].z + c * q4[k].z;
                    np.w = c * p4[k].w - sn * q4[k].w;  nq.w = sn * p4[k].w + c * q4[k].w;
                    *(float4*)(bp + k * 32) = np;
                    *(float4*)(bq + k * 32) = nq;
                }
                if (sub == 0) {
                    nrm2[p] = al - t * g;
                    nrm2[q] = be + t * g;
                    any_rot = 1;          // benign same-value race
                }
            }
            __syncthreads();
        }

        // early exit: last round's barrier makes any_rot coherent here.
        int rot = any_rot;
        __syncthreads();          // protect against next sweep's reset racing
        if (!rot) break;
    }

    // final exact norms (||b_k||^2 = lambda_k^2)
    {
        int col = tid >> 2, part = tid & 3;
        const float* bc = B + col * 128;
        float ss = 0.f;
#pragma unroll
        for (int k = 0; k < 8; k++) {
            float4 v = *(const float4*)(bc + (k * 4 + part) * 4);
            ss += v.x * v.x + v.y * v.y + v.z * v.z + v.w * v.w;
        }
        ss += __shfl_xor_sync(0xffffffffu, ss, 1);
        ss += __shfl_xor_sync(0xffffffffu, ss, 2);
        if (part == 0) nrm2[col] = ss;
    }
    __syncthreads();

    // select top-RANK columns by norm; weight = 1/||b||^2 so P = sum w b b^T
    if (tid < 128) {
        float nj = nrm2[tid];
        int rk = 0;
        for (int i = 0; i < 128; i++) {
            float ni = nrm2[i];
            rk += (ni > nj) || (ni == nj && i < tid);
        }
        wsel[tid] = (rk < RANK) ? 1.f / nj : 0.f;
    }
    __syncthreads();

    // P[r][c] = sum_j w_j * B[j][r] * B[j][c]
    {
        int tx = tid & 31, ty = tid >> 5;     // 32 x 16 thread grid
        int c0 = tx * 4, r0 = ty * 8;
        float acc[8][4];
#pragma unroll
        for (int i = 0; i < 8; i++)
#pragma unroll
            for (int l = 0; l < 4; l++) acc[i][l] = 0.f;

        for (int j = 0; j < 128; j++) {
            float wj = wsel[j];
            if (wj == 0.f) continue;          // uniform branch: halves work
            const float* bj = B + j * 128;
            float br[8];
            *(float4*)(br)     = *(const float4*)(bj + r0);
            *(float4*)(br + 4) = *(const float4*)(bj + r0 + 4);
            float4 bc4 = *(const float4*)(bj + c0);
            bc4.x *= wj; bc4.y *= wj; bc4.z *= wj; bc4.w *= wj;
#pragma unroll
            for (int i = 0; i < 8; i++) {
                acc[i][0] += br[i] * bc4.x;
                acc[i][1] += br[i] * bc4.y;
                acc[i][2] += br[i] * bc4.z;
                acc[i][3] += br[i] * bc4.w;
            }
        }
        float* Pm = g_P + (size_t)m * DDIM * DDIM;
#pragma unroll
        for (int i = 0; i < 8; i++)
            *(float4*)(Pm + (r0 + i) * 128 + c0) =
                make_float4(acc[i][0], acc[i][1], acc[i][2], acc[i][3]);
    }
}

// ---------------------------------------------------------------------------
// Kernel 3: out = X @ P  (fp32, FFMA2 inner loop). grid (32, NMAT),
// 256 threads, 64-row tiles; k unrolled by 4 with float4 A loads.
// ---------------------------------------------------------------------------
__global__ __launch_bounds__(256) void recon_kernel(const float* __restrict__ X,
                                                    float* __restrict__ out)
{
    extern __shared__ float sm[];
    float* Ps = sm;          // 128*128
    float* Xs = sm + 16384;  // 64*128
    const int m  = blockIdx.y;
    const int s0 = blockIdx.x * 64;
    const int tid = threadIdx.x;

    const float* Pm = g_P + (size_t)m * DDIM * DDIM;
#pragma unroll
    for (int k = 0; k < 16; k++) {
        int i4 = tid + k * 256;
        *(float4*)(Ps + i4 * 4) = *(const float4*)(Pm + i4 * 4);
    }
    const float* Xm = X + (size_t)m * SLEN * DDIM + (size_t)s0 * DDIM;
#pragma unroll
    for (int k = 0; k < 8; k++) {
        int i4 = tid + k * 256;
        *(float4*)(Xs + i4 * 4) = *(const float4*)(Xm + i4 * 4);
    }
    __syncthreads();

    const int tx = tid & 31, ty = tid >> 5;   // 32 x 8
    const int c0 = tx * 4, r0 = ty * 8;
    u64 acc2[8][2];
#pragma unroll
    for (int i = 0; i < 8; i++) { acc2[i][0] = 0ULL; acc2[i][1] = 0ULL; }

#pragma unroll 1
    for (int k0 = 0; k0 < 128; k0 += 4) {
        float4 a4[8];
#pragma unroll
        for (int i = 0; i < 8; i++)
            a4[i] = *(const float4*)(Xs + (r0 + i) * 128 + k0);
#pragma unroll
        for (int kk = 0; kk < 4; kk++) {
            const u64* bp = (const u64*)(Ps + (k0 + kk) * 128 + c0);
            u64 b0 = bp[0], b1 = bp[1];
#pragma unroll
            for (int i = 0; i < 8; i++) {
                float av = (kk == 0) ? a4[i].x : (kk == 1) ? a4[i].y
                         : (kk == 2) ? a4[i].z : a4[i].w;
                u64 a2 = pk2(av, av);
                acc2[i][0] = fma2(a2, b0, acc2[i][0]);
                acc2[i][1] = fma2(a2, b1, acc2[i][1]);
            }
        }
    }

    float* outm = out + (size_t)m * SLEN * DDIM + (size_t)s0 * DDIM;
#pragma unroll
    for (int i = 0; i < 8; i++) {
        float x0, x1, x2, x3;
        upk2(acc2[i][0], x0, x1); upk2(acc2[i][1], x2, x3);
        *(float4*)(outm + (r0 + i) * 128 + c0) = make_float4(x0, x1, x2, x3);
    }
}

// ---------------------------------------------------------------------------
extern "C" void kernel_launch(void* const* d_in, const int* in_sizes, int n_in,
                              void* d_out, int out_size)
{
    const float* X = (const float*)d_in[0];
    float* out = (float*)d_out;

    cudaFuncSetAttribute(jacobi_kernel, cudaFuncAttributeMaxDynamicSharedMemorySize,
                         128 * 128 * 4);
    cudaFuncSetAttribute(recon_kernel, cudaFuncAttributeMaxDynamicSharedMemorySize,
                         (16384 + 8192) * 4);

    gram_partial_kernel<<<dim3(KCH, NMAT), 256>>>(X);
    jacobi_kernel<<<NMAT, 512, 128 * 128 * 4>>>();
    recon_kernel<<<dim3(SLEN / 64, NMAT), 256, (16384 + 8192) * 4>>>(X, out);
}